// round 6
// baseline (speedup 1.0000x reference)
#include <cuda_runtime.h>
#include <math.h>

// ============================================================================
// MNIST_CNN2D_TWN forward pass, f32, fully fused pipeline.
//
// Pipeline:
//  0. zero stats
//  1. quantize w1/w2/wf1/wf2 (threshold = 0.05*max|w|), w2 transposed to
//     [ic][ky][kx][oc] for vectorized smem loads.
//  2. conv1(5x5,1->32) + bias + per-channel sum/sumsq (pre-pool) + maxpool2
//     -> g_pool1 [N,32,12,12]   (bn applied lazily: relu(a1*x+d1))
//  3. finalize bn1 affine (a1,d1)
//  4. conv2(5x5,32->64) on relu(a1*pool1+d1) + bias + stats + maxpool2
//     -> g_pool2 [N,64,4,4]
//  5. finalize bn2 affine
//  6. fc1: [4096,1024]x[1024,512] tiled SGEMM, A = relu(a2*pool2+d2) on load,
//     epilogue: +bf1, write z, per-column sum/sumsq
//  7. finalize bn3 affine
//  8. fc2: relu(a3*z+d3) @ qf2^T + bf2 -> out [4096,10]
//
// Legality of pool/bn swap: g=1>0 so bn is increasing affine; relu monotone;
// hence maxpool(relu(bn(x))) == relu(bn(maxpool(x))). Stats are still taken
// over the full pre-pool conv outputs, matching the reference exactly.
// ============================================================================

#define NIMG 4096

// ---------------- device scratch (static; no allocation) ----------------
__device__ float g_q1[800];                      // [32][25] ternary
__device__ float g_q2t[51200];                   // [(ic*25+kk)][64] ternary (transposed)
__device__ float g_qf1[524288];                  // [512][1024] ternary
__device__ float g_qf2[5120];                    // [10][512] ternary
__device__ float g_pool1[(size_t)NIMG * 32 * 144]; // raw pooled conv1 (pre-bn)
__device__ float g_pool2[(size_t)NIMG * 64 * 16];  // raw pooled conv2 (pre-bn)
__device__ float g_z[(size_t)NIMG * 512];          // fc1 pre-bn output
__device__ float g_sum1[32], g_sq1[32], g_a1[32], g_d1[32];
__device__ float g_sum2[64], g_sq2[64], g_a2[64], g_d2[64];
__device__ float g_sum3[512], g_sq3[512], g_a3[512], g_d3[512];

// ---------------- stats zeroing ----------------
__global__ void zero_stats_kernel() {
    int i = threadIdx.x;
    if (i < 32) { g_sum1[i] = 0.f; g_sq1[i] = 0.f; }
    if (i < 64) { g_sum2[i] = 0.f; g_sq2[i] = 0.f; }
    for (int j = i; j < 512; j += blockDim.x) { g_sum3[j] = 0.f; g_sq3[j] = 0.f; }
}

// ---------------- ternary quantization (single block, 2 phases) ----------------
__device__ __forceinline__ float block_maxabs(const float* __restrict__ w, int n) {
    __shared__ float red[32];
    int tid = threadIdx.x;
    float m = 0.f;
    for (int i = tid; i < n; i += blockDim.x) m = fmaxf(m, fabsf(w[i]));
    #pragma unroll
    for (int o = 16; o; o >>= 1) m = fmaxf(m, __shfl_xor_sync(0xffffffffu, m, o));
    if ((tid & 31) == 0) red[tid >> 5] = m;
    __syncthreads();
    if (tid < 32) {
        float v = (tid < (int)((blockDim.x + 31) >> 5)) ? red[tid] : 0.f;
        #pragma unroll
        for (int o = 16; o; o >>= 1) v = fmaxf(v, __shfl_xor_sync(0xffffffffu, v, o));
        if (tid == 0) red[0] = v;
    }
    __syncthreads();
    return red[0];
}

// which: 0 -> g_q1 (n=800), 2 -> g_qf1, 3 -> g_qf2
__global__ void quant_kernel(const float* __restrict__ w, int n, int which) {
    float t = 0.05f * block_maxabs(w, n);
    float* q = (which == 0) ? g_q1 : (which == 2) ? g_qf1 : g_qf2;
    for (int i = threadIdx.x; i < n; i += blockDim.x) {
        float v = w[i];
        q[i] = (v > t ? 1.f : 0.f) - (v < -t ? 1.f : 0.f);
    }
}

// w2 [oc=64][ic=32][5][5] -> g_q2t[(ic*25+kk)*64 + oc]
__global__ void quant_w2_kernel(const float* __restrict__ w) {
    const int n = 51200;
    float t = 0.05f * block_maxabs(w, n);
    for (int i = threadIdx.x; i < n; i += blockDim.x) {
        float v = w[i];
        float q = (v > t ? 1.f : 0.f) - (v < -t ? 1.f : 0.f);
        int oc = i / 800;
        int rem = i - oc * 800;
        g_q2t[rem * 64 + oc] = q;
    }
}

// ---------------- bn affine finalize: a = g/sqrt(var+eps), d = be - mean*a ----
__global__ void finalize_kernel(const float* __restrict__ gam,
                                const float* __restrict__ bet, int which) {
    const float* sum; const float* sq; float* a; float* d; int C; float inv;
    if (which == 0)      { sum = g_sum1; sq = g_sq1; a = g_a1; d = g_d1; C = 32;  inv = 1.f / 2359296.f; }
    else if (which == 1) { sum = g_sum2; sq = g_sq2; a = g_a2; d = g_d2; C = 64;  inv = 1.f / 262144.f;  }
    else                 { sum = g_sum3; sq = g_sq3; a = g_a3; d = g_d3; C = 512; inv = 1.f / 4096.f;    }
    int i = blockIdx.x * blockDim.x + threadIdx.x;
    if (i < C) {
        float m = sum[i] * inv;
        float v = sq[i] * inv - m * m;
        float ai = gam[i] / sqrtf(v + 1e-5f);
        a[i] = ai;
        d[i] = bet[i] - m * ai;
    }
}

// ---------------- conv1: 1->32, 5x5, + bias + stats + maxpool2 ----------------
// grid = NIMG, block = 256 (thread: channel c = tid>>3, 18 pooled cells each)
__global__ __launch_bounds__(256) void conv1_kernel(const float* __restrict__ x,
                                                    const float* __restrict__ b1) {
    __shared__ float img[784];
    __shared__ float wsh[800];
    __shared__ float ssum[32], ssq[32];
    int n = blockIdx.x, tid = threadIdx.x;

    for (int i = tid; i < 784; i += 256) img[i] = x[(size_t)n * 784 + i];
    for (int i = tid; i < 800; i += 256) wsh[i] = g_q1[i];
    if (tid < 32) { ssum[tid] = 0.f; ssq[tid] = 0.f; }
    __syncthreads();

    int c = tid >> 3, sub = tid & 7;
    float wr[25];
    #pragma unroll
    for (int k = 0; k < 25; k++) wr[k] = wsh[c * 25 + k];
    float bias = b1[c];
    float lsum = 0.f, lsq = 0.f;
    float* outp = g_pool1 + ((size_t)n * 32 + c) * 144;

    for (int k2 = 0; k2 < 18; k2++) {           // 144 pooled cells / 8 subs
        int p = sub * 18 + k2;
        int py = p / 12, px = p - py * 12;
        int oy = 2 * py, ox = 2 * px;
        float win[36];                           // 6x6 window in registers
        #pragma unroll
        for (int r = 0; r < 6; r++)
            #pragma unroll
            for (int cc = 0; cc < 6; cc++)
                win[r * 6 + cc] = img[(oy + r) * 28 + ox + cc];
        float mx = -1e30f;
        #pragma unroll
        for (int dy = 0; dy < 2; dy++)
            #pragma unroll
            for (int dx = 0; dx < 2; dx++) {
                float acc = bias;
                #pragma unroll
                for (int ky = 0; ky < 5; ky++)
                    #pragma unroll
                    for (int kx = 0; kx < 5; kx++)
                        acc = fmaf(win[(dy + ky) * 6 + dx + kx], wr[ky * 5 + kx], acc);
                lsum += acc;
                lsq = fmaf(acc, acc, lsq);
                mx = fmaxf(mx, acc);
            }
        outp[p] = mx;
    }
    atomicAdd(&ssum[c], lsum);
    atomicAdd(&ssq[c], lsq);
    __syncthreads();
    if (tid < 32) { atomicAdd(&g_sum1[tid], ssum[tid]); atomicAdd(&g_sq1[tid], ssq[tid]); }
}

// ---------------- conv2: 32->64, 5x5, + bias + stats + maxpool2 ----------------
// grid = NIMG, block = 256: thread = (oc group of 4) x (2x2 raw = 1 pooled cell)
__global__ __launch_bounds__(256) void conv2_kernel(const float* __restrict__ b2) {
    __shared__ __align__(16) float ish[4608];    // relu(bn(pool1)) for this image
    __shared__ __align__(16) float wt[6400];     // 4 ic x 25 x 64 oc weight tile
    __shared__ float ssum[64], ssq[64];
    int n = blockIdx.x, tid = threadIdx.x;

    for (int i = tid; i < 4608; i += 256) {
        int c = i / 144;
        float raw = g_pool1[(size_t)n * 4608 + i];
        ish[i] = fmaxf(fmaf(g_a1[c], raw, g_d1[c]), 0.f);
    }
    if (tid < 64) { ssum[tid] = 0.f; ssq[tid] = 0.f; }

    int oc4 = tid >> 4;                  // 0..15, ocs = oc4*4 .. +3
    int pg = tid & 15, ty = pg >> 2, tx = pg & 3;
    int y0 = 2 * ty, x0 = 2 * tx;        // raw output 2x2 tile origin (8x8 grid)

    float acc[4][2][2];
    #pragma unroll
    for (int q = 0; q < 4; q++)
        #pragma unroll
        for (int dy = 0; dy < 2; dy++)
            #pragma unroll
            for (int dx = 0; dx < 2; dx++) acc[q][dy][dx] = 0.f;

    for (int icb = 0; icb < 8; icb++) {          // ic tiles of 4
        __syncthreads();
        for (int i = tid; i < 6400; i += 256) wt[i] = g_q2t[icb * 6400 + i];
        __syncthreads();
        for (int icl = 0; icl < 4; icl++) {
            int base = (icb * 4 + icl) * 144;
            #pragma unroll
            for (int ky = 0; ky < 5; ky++) {
                float r0[6], r1[6];
                int rb = base + (y0 + ky) * 12 + x0;
                #pragma unroll
                for (int j = 0; j < 6; j++) { r0[j] = ish[rb + j]; r1[j] = ish[rb + 12 + j]; }
                #pragma unroll
                for (int kx = 0; kx < 5; kx++) {
                    float4 w4 = *reinterpret_cast<const float4*>(
                        &wt[(((icl * 5 + ky) * 5 + kx) << 6) + (oc4 << 2)]);
                    float i00 = r0[kx], i01 = r0[kx + 1];
                    float i10 = r1[kx], i11 = r1[kx + 1];
                    acc[0][0][0] = fmaf(i00, w4.x, acc[0][0][0]);
                    acc[0][0][1] = fmaf(i01, w4.x, acc[0][0][1]);
                    acc[0][1][0] = fmaf(i10, w4.x, acc[0][1][0]);
                    acc[0][1][1] = fmaf(i11, w4.x, acc[0][1][1]);
                    acc[1][0][0] = fmaf(i00, w4.y, acc[1][0][0]);
                    acc[1][0][1] = fmaf(i01, w4.y, acc[1][0][1]);
                    acc[1][1][0] = fmaf(i10, w4.y, acc[1][1][0]);
                    acc[1][1][1] = fmaf(i11, w4.y, acc[1][1][1]);
                    acc[2][0][0] = fmaf(i00, w4.z, acc[2][0][0]);
                    acc[2][0][1] = fmaf(i01, w4.z, acc[2][0][1]);
                    acc[2][1][0] = fmaf(i10, w4.z, acc[2][1][0]);
                    acc[2][1][1] = fmaf(i11, w4.z, acc[2][1][1]);
                    acc[3][0][0] = fmaf(i00, w4.w, acc[3][0][0]);
                    acc[3][0][1] = fmaf(i01, w4.w, acc[3][0][1]);
                    acc[3][1][0] = fmaf(i10, w4.w, acc[3][1][0]);
                    acc[3][1][1] = fmaf(i11, w4.w, acc[3][1][1]);
                }
            }
        }
    }

    #pragma unroll
    for (int q = 0; q < 4; q++) {
        int oc = oc4 * 4 + q;
        float bias = b2[oc];
        float mx = -1e30f, ls = 0.f, lq = 0.f;
        #pragma unroll
        for (int dy = 0; dy < 2; dy++)
            #pragma unroll
            for (int dx = 0; dx < 2; dx++) {
                float v = acc[q][dy][dx] + bias;
                ls += v;
                lq = fmaf(v, v, lq);
                mx = fmaxf(mx, v);
            }
        g_pool2[((size_t)n * 64 + oc) * 16 + ty * 4 + tx] = mx;
        atomicAdd(&ssum[oc], ls);
        atomicAdd(&ssq[oc], lq);
    }
    __syncthreads();
    if (tid < 64) { atomicAdd(&g_sum2[tid], ssum[tid]); atomicAdd(&g_sq2[tid], ssq[tid]); }
}

// ---------------- fc1: tiled SGEMM 128x64x16, A = relu(bn(pool2)) on load -----
// grid (32,8), block 256; micro-tile 8(m) x 4(n) per thread
__global__ __launch_bounds__(256) void fc1_kernel(const float* __restrict__ bf1) {
    __shared__ __align__(16) float As[16 * 132];  // [k][m], padded
    __shared__ __align__(16) float Bs[16 * 68];   // [k][j], padded
    __shared__ float cs[64], cq[64];
    int tid = threadIdx.x;
    int m0 = blockIdx.x * 128, j0 = blockIdx.y * 64;
    int ty = tid >> 4, tx = tid & 15;
    if (tid < 64) { cs[tid] = 0.f; cq[tid] = 0.f; }

    float c[8][4];
    #pragma unroll
    for (int r = 0; r < 8; r++)
        #pragma unroll
        for (int q = 0; q < 4; q++) c[r][q] = 0.f;

    for (int kt = 0; kt < 64; kt++) {            // k-tile == channel (16 elems)
        float sc = g_a2[kt], sd = g_d2[kt];
        #pragma unroll
        for (int s = 0; s < 8; s++) {
            int idx = s * 256 + tid, ml = idx >> 4, kl = idx & 15;
            float raw = g_pool2[(size_t)(m0 + ml) * 1024 + kt * 16 + kl];
            As[kl * 132 + ml] = fmaxf(fmaf(sc, raw, sd), 0.f);
        }
        #pragma unroll
        for (int s = 0; s < 4; s++) {
            int idx = s * 256 + tid, jl = idx >> 4, kl = idx & 15;
            Bs[kl * 68 + jl] = g_qf1[(size_t)(j0 + jl) * 1024 + kt * 16 + kl];
        }
        __syncthreads();
        #pragma unroll
        for (int k = 0; k < 16; k++) {
            float4 a0 = *reinterpret_cast<const float4*>(&As[k * 132 + ty * 8]);
            float4 a1 = *reinterpret_cast<const float4*>(&As[k * 132 + ty * 8 + 4]);
            float4 b  = *reinterpret_cast<const float4*>(&Bs[k * 68 + tx * 4]);
            float av[8] = {a0.x, a0.y, a0.z, a0.w, a1.x, a1.y, a1.z, a1.w};
            float bv[4] = {b.x, b.y, b.z, b.w};
            #pragma unroll
            for (int r = 0; r < 8; r++)
                #pragma unroll
                for (int q = 0; q < 4; q++) c[r][q] = fmaf(av[r], bv[q], c[r][q]);
        }
        __syncthreads();
    }

    float bias[4], ls[4] = {0, 0, 0, 0}, lq[4] = {0, 0, 0, 0};
    #pragma unroll
    for (int q = 0; q < 4; q++) bias[q] = bf1[j0 + tx * 4 + q];
    #pragma unroll
    for (int r = 0; r < 8; r++) {
        size_t row = (size_t)(m0 + ty * 8 + r);
        #pragma unroll
        for (int q = 0; q < 4; q++) {
            float v = c[r][q] + bias[q];
            g_z[row * 512 + j0 + tx * 4 + q] = v;
            ls[q] += v;
            lq[q] = fmaf(v, v, lq[q]);
        }
    }
    #pragma unroll
    for (int q = 0; q < 4; q++) { atomicAdd(&cs[tx * 4 + q], ls[q]); atomicAdd(&cq[tx * 4 + q], lq[q]); }
    __syncthreads();
    if (tid < 64) { atomicAdd(&g_sum3[j0 + tid], cs[tid]); atomicAdd(&g_sq3[j0 + tid], cq[tid]); }
}

// ---------------- fc2: [4096,512] x [512,10], one warp per row ----------------
__global__ __launch_bounds__(256) void fc2_kernel(const float* __restrict__ bf2,
                                                  float* __restrict__ out) {
    int w = threadIdx.x >> 5, l = threadIdx.x & 31;
    int row = blockIdx.x * 8 + w;
    const float* zr = g_z + (size_t)row * 512;
    float acc[10];
    #pragma unroll
    for (int k = 0; k < 10; k++) acc[k] = 0.f;
    for (int j = l; j < 512; j += 32) {
        float h = fmaxf(fmaf(g_a3[j], zr[j], g_d3[j]), 0.f);
        #pragma unroll
        for (int k = 0; k < 10; k++) acc[k] = fmaf(h, g_qf2[k * 512 + j], acc[k]);
    }
    #pragma unroll
    for (int k = 0; k < 10; k++)
        #pragma unroll
        for (int o = 16; o; o >>= 1) acc[k] += __shfl_xor_sync(0xffffffffu, acc[k], o);
    if (l < 10) out[row * 10 + l] = acc[l] + bf2[l];
}

// ---------------- host entry ----------------
extern "C" void kernel_launch(void* const* d_in, const int* in_sizes, int n_in,
                              void* d_out, int out_size) {
    const float* x   = (const float*)d_in[0];
    const float* w1  = (const float*)d_in[1];
    const float* b1  = (const float*)d_in[2];
    const float* g1  = (const float*)d_in[3];
    const float* be1 = (const float*)d_in[4];
    const float* w2  = (const float*)d_in[5];
    const float* b2  = (const float*)d_in[6];
    const float* g2  = (const float*)d_in[7];
    const float* be2 = (const float*)d_in[8];
    const float* wf1 = (const float*)d_in[9];
    const float* bf1 = (const float*)d_in[10];
    const float* g3  = (const float*)d_in[11];
    const float* be3 = (const float*)d_in[12];
    const float* wf2 = (const float*)d_in[13];
    const float* bf2 = (const float*)d_in[14];
    float* out = (float*)d_out;

    zero_stats_kernel<<<1, 512>>>();
    quant_kernel<<<1, 1024>>>(w1, 800, 0);
    quant_w2_kernel<<<1, 1024>>>(w2);
    quant_kernel<<<1, 1024>>>(wf1, 524288, 2);
    quant_kernel<<<1, 1024>>>(wf2, 5120, 3);

    conv1_kernel<<<NIMG, 256>>>(x, b1);
    finalize_kernel<<<1, 32>>>(g1, be1, 0);

    conv2_kernel<<<NIMG, 256>>>(b2);
    finalize_kernel<<<1, 64>>>(g2, be2, 1);

    fc1_kernel<<<dim3(32, 8), 256>>>(bf1);
    finalize_kernel<<<2, 256>>>(g3, be3, 2);

    fc2_kernel<<<512, 256>>>(bf2, out);
}

// round 7
// speedup vs baseline: 1.3840x; 1.3840x over previous
#include <cuda_runtime.h>
#include <math.h>

// ============================================================================
// MNIST_CNN2D_TWN forward pass, f32, fully fused pipeline.
//
// R6 change: quantization parallelized. Previously single-block quant_kernel
// on wf1 (2MB, two serial passes) took 321.7us (26% of runtime, 1 SM busy).
// Now: grid-wide maxabs reduction (atomicMax on uint bits, deterministic)
// + grid-wide quantize pass. Expected quant stage: ~350us -> ~15us.
//
// Pipeline:
//  0. zero stats + thresholds
//  1. maxabs(w1/w2/wf1/wf2) -> g_tmax[4]; quantize each (w2 transposed to
//     [ic][ky][kx][oc] for vectorized smem loads).
//  2. conv1(5x5,1->32) + bias + per-channel sum/sumsq (pre-pool) + maxpool2
//     -> g_pool1 [N,32,12,12]   (bn applied lazily: relu(a1*x+d1))
//  3. finalize bn1 affine (a1,d1)
//  4. conv2(5x5,32->64) on relu(a1*pool1+d1) + bias + stats + maxpool2
//  5. finalize bn2 affine
//  6. fc1: tiled SGEMM, A = relu(a2*pool2+d2) on load, epilogue +bf1,
//     write z, per-column sum/sumsq
//  7. finalize bn3 affine
//  8. fc2: relu(a3*z+d3) @ qf2^T + bf2 -> out [4096,10]
//
// Legality of pool/bn swap: g=1>0 so bn is increasing affine; relu monotone;
// hence maxpool(relu(bn(x))) == relu(bn(maxpool(x))). Stats are still taken
// over the full pre-pool conv outputs, matching the reference exactly.
// ============================================================================

#define NIMG 4096

// ---------------- device scratch (static; no allocation) ----------------
__device__ float g_q1[800];                      // [32][25] ternary
__device__ float g_q2t[51200];                   // [(ic*25+kk)][64] ternary (transposed)
__device__ float g_qf1[524288];                  // [512][1024] ternary
__device__ float g_qf2[5120];                    // [10][512] ternary
__device__ float g_pool1[(size_t)NIMG * 32 * 144]; // raw pooled conv1 (pre-bn)
__device__ float g_pool2[(size_t)NIMG * 64 * 16];  // raw pooled conv2 (pre-bn)
__device__ float g_z[(size_t)NIMG * 512];          // fc1 pre-bn output
__device__ float g_sum1[32], g_sq1[32], g_a1[32], g_d1[32];
__device__ float g_sum2[64], g_sq2[64], g_a2[64], g_d2[64];
__device__ float g_sum3[512], g_sq3[512], g_a3[512], g_d3[512];
__device__ unsigned g_tmax[4];                   // maxabs bit patterns (w1,w2,wf1,wf2)

// ---------------- stats zeroing ----------------
__global__ void zero_stats_kernel() {
    int i = threadIdx.x;
    if (i < 32) { g_sum1[i] = 0.f; g_sq1[i] = 0.f; }
    if (i < 64) { g_sum2[i] = 0.f; g_sq2[i] = 0.f; }
    if (i < 4)  { g_tmax[i] = 0u; }
    for (int j = i; j < 512; j += blockDim.x) { g_sum3[j] = 0.f; g_sq3[j] = 0.f; }
}

// ---------------- grid-wide maxabs reduction ----------------
// Non-negative floats compare identically as unsigned ints; max is
// order-independent, so atomicMax is deterministic.
__global__ void maxabs_kernel(const float* __restrict__ w, int n, int which) {
    __shared__ float red[8];
    int tid = threadIdx.x;
    float m = 0.f;
    for (int i = blockIdx.x * blockDim.x + tid; i < n; i += gridDim.x * blockDim.x)
        m = fmaxf(m, fabsf(w[i]));
    #pragma unroll
    for (int o = 16; o; o >>= 1) m = fmaxf(m, __shfl_xor_sync(0xffffffffu, m, o));
    if ((tid & 31) == 0) red[tid >> 5] = m;
    __syncthreads();
    if (tid < 32) {
        float v = (tid < (int)(blockDim.x >> 5)) ? red[tid] : 0.f;
        #pragma unroll
        for (int o = 4; o; o >>= 1) v = fmaxf(v, __shfl_xor_sync(0xffffffffu, v, o));
        if (tid == 0) atomicMax(&g_tmax[which], __float_as_uint(v));
    }
}

// which: 0 -> g_q1 (n=800), 2 -> g_qf1, 3 -> g_qf2
__global__ void quantize_kernel(const float* __restrict__ w, int n, int which) {
    float t = 0.05f * __uint_as_float(g_tmax[which]);
    float* q = (which == 0) ? g_q1 : (which == 2) ? g_qf1 : g_qf2;
    int i = blockIdx.x * blockDim.x + threadIdx.x;
    if (i < n) {
        float v = w[i];
        q[i] = (v > t ? 1.f : 0.f) - (v < -t ? 1.f : 0.f);
    }
}

// w2 [oc=64][ic=32][5][5] -> g_q2t[(ic*25+kk)*64 + oc]
__global__ void quantize_w2_kernel(const float* __restrict__ w) {
    float t = 0.05f * __uint_as_float(g_tmax[1]);
    int i = blockIdx.x * blockDim.x + threadIdx.x;
    if (i < 51200) {
        float v = w[i];
        float q = (v > t ? 1.f : 0.f) - (v < -t ? 1.f : 0.f);
        int oc = i / 800;
        int rem = i - oc * 800;
        g_q2t[rem * 64 + oc] = q;
    }
}

// ---------------- bn affine finalize: a = g/sqrt(var+eps), d = be - mean*a ----
__global__ void finalize_kernel(const float* __restrict__ gam,
                                const float* __restrict__ bet, int which) {
    const float* sum; const float* sq; float* a; float* d; int C; float inv;
    if (which == 0)      { sum = g_sum1; sq = g_sq1; a = g_a1; d = g_d1; C = 32;  inv = 1.f / 2359296.f; }
    else if (which == 1) { sum = g_sum2; sq = g_sq2; a = g_a2; d = g_d2; C = 64;  inv = 1.f / 262144.f;  }
    else                 { sum = g_sum3; sq = g_sq3; a = g_a3; d = g_d3; C = 512; inv = 1.f / 4096.f;    }
    int i = blockIdx.x * blockDim.x + threadIdx.x;
    if (i < C) {
        float m = sum[i] * inv;
        float v = sq[i] * inv - m * m;
        float ai = gam[i] / sqrtf(v + 1e-5f);
        a[i] = ai;
        d[i] = bet[i] - m * ai;
    }
}

// ---------------- conv1: 1->32, 5x5, + bias + stats + maxpool2 ----------------
// grid = NIMG, block = 256 (thread: channel c = tid>>3, 18 pooled cells each)
__global__ __launch_bounds__(256) void conv1_kernel(const float* __restrict__ x,
                                                    const float* __restrict__ b1) {
    __shared__ float img[784];
    __shared__ float wsh[800];
    __shared__ float ssum[32], ssq[32];
    int n = blockIdx.x, tid = threadIdx.x;

    for (int i = tid; i < 784; i += 256) img[i] = x[(size_t)n * 784 + i];
    for (int i = tid; i < 800; i += 256) wsh[i] = g_q1[i];
    if (tid < 32) { ssum[tid] = 0.f; ssq[tid] = 0.f; }
    __syncthreads();

    int c = tid >> 3, sub = tid & 7;
    float wr[25];
    #pragma unroll
    for (int k = 0; k < 25; k++) wr[k] = wsh[c * 25 + k];
    float bias = b1[c];
    float lsum = 0.f, lsq = 0.f;
    float* outp = g_pool1 + ((size_t)n * 32 + c) * 144;

    for (int k2 = 0; k2 < 18; k2++) {           // 144 pooled cells / 8 subs
        int p = sub * 18 + k2;
        int py = p / 12, px = p - py * 12;
        int oy = 2 * py, ox = 2 * px;
        float win[36];                           // 6x6 window in registers
        #pragma unroll
        for (int r = 0; r < 6; r++)
            #pragma unroll
            for (int cc = 0; cc < 6; cc++)
                win[r * 6 + cc] = img[(oy + r) * 28 + ox + cc];
        float mx = -1e30f;
        #pragma unroll
        for (int dy = 0; dy < 2; dy++)
            #pragma unroll
            for (int dx = 0; dx < 2; dx++) {
                float acc = bias;
                #pragma unroll
                for (int ky = 0; ky < 5; ky++)
                    #pragma unroll
                    for (int kx = 0; kx < 5; kx++)
                        acc = fmaf(win[(dy + ky) * 6 + dx + kx], wr[ky * 5 + kx], acc);
                lsum += acc;
                lsq = fmaf(acc, acc, lsq);
                mx = fmaxf(mx, acc);
            }
        outp[p] = mx;
    }
    atomicAdd(&ssum[c], lsum);
    atomicAdd(&ssq[c], lsq);
    __syncthreads();
    if (tid < 32) { atomicAdd(&g_sum1[tid], ssum[tid]); atomicAdd(&g_sq1[tid], ssq[tid]); }
}

// ---------------- conv2: 32->64, 5x5, + bias + stats + maxpool2 ----------------
// grid = NIMG, block = 256: thread = (oc group of 4) x (2x2 raw = 1 pooled cell)
__global__ __launch_bounds__(256) void conv2_kernel(const float* __restrict__ b2) {
    __shared__ __align__(16) float ish[4608];    // relu(bn(pool1)) for this image
    __shared__ __align__(16) float wt[6400];     // 4 ic x 25 x 64 oc weight tile
    __shared__ float ssum[64], ssq[64];
    int n = blockIdx.x, tid = threadIdx.x;

    for (int i = tid; i < 4608; i += 256) {
        int c = i / 144;
        float raw = g_pool1[(size_t)n * 4608 + i];
        ish[i] = fmaxf(fmaf(g_a1[c], raw, g_d1[c]), 0.f);
    }
    if (tid < 64) { ssum[tid] = 0.f; ssq[tid] = 0.f; }

    int oc4 = tid >> 4;                  // 0..15, ocs = oc4*4 .. +3
    int pg = tid & 15, ty = pg >> 2, tx = pg & 3;
    int y0 = 2 * ty, x0 = 2 * tx;        // raw output 2x2 tile origin (8x8 grid)

    float acc[4][2][2];
    #pragma unroll
    for (int q = 0; q < 4; q++)
        #pragma unroll
        for (int dy = 0; dy < 2; dy++)
            #pragma unroll
            for (int dx = 0; dx < 2; dx++) acc[q][dy][dx] = 0.f;

    for (int icb = 0; icb < 8; icb++) {          // ic tiles of 4
        __syncthreads();
        for (int i = tid; i < 6400; i += 256) wt[i] = g_q2t[icb * 6400 + i];
        __syncthreads();
        for (int icl = 0; icl < 4; icl++) {
            int base = (icb * 4 + icl) * 144;
            #pragma unroll
            for (int ky = 0; ky < 5; ky++) {
                float r0[6], r1[6];
                int rb = base + (y0 + ky) * 12 + x0;
                #pragma unroll
                for (int j = 0; j < 6; j++) { r0[j] = ish[rb + j]; r1[j] = ish[rb + 12 + j]; }
                #pragma unroll
                for (int kx = 0; kx < 5; kx++) {
                    float4 w4 = *reinterpret_cast<const float4*>(
                        &wt[(((icl * 5 + ky) * 5 + kx) << 6) + (oc4 << 2)]);
                    float i00 = r0[kx], i01 = r0[kx + 1];
                    float i10 = r1[kx], i11 = r1[kx + 1];
                    acc[0][0][0] = fmaf(i00, w4.x, acc[0][0][0]);
                    acc[0][0][1] = fmaf(i01, w4.x, acc[0][0][1]);
                    acc[0][1][0] = fmaf(i10, w4.x, acc[0][1][0]);
                    acc[0][1][1] = fmaf(i11, w4.x, acc[0][1][1]);
                    acc[1][0][0] = fmaf(i00, w4.y, acc[1][0][0]);
                    acc[1][0][1] = fmaf(i01, w4.y, acc[1][0][1]);
                    acc[1][1][0] = fmaf(i10, w4.y, acc[1][1][0]);
                    acc[1][1][1] = fmaf(i11, w4.y, acc[1][1][1]);
                    acc[2][0][0] = fmaf(i00, w4.z, acc[2][0][0]);
                    acc[2][0][1] = fmaf(i01, w4.z, acc[2][0][1]);
                    acc[2][1][0] = fmaf(i10, w4.z, acc[2][1][0]);
                    acc[2][1][1] = fmaf(i11, w4.z, acc[2][1][1]);
                    acc[3][0][0] = fmaf(i00, w4.w, acc[3][0][0]);
                    acc[3][0][1] = fmaf(i01, w4.w, acc[3][0][1]);
                    acc[3][1][0] = fmaf(i10, w4.w, acc[3][1][0]);
                    acc[3][1][1] = fmaf(i11, w4.w, acc[3][1][1]);
                }
            }
        }
    }

    #pragma unroll
    for (int q = 0; q < 4; q++) {
        int oc = oc4 * 4 + q;
        float bias = b2[oc];
        float mx = -1e30f, ls = 0.f, lq = 0.f;
        #pragma unroll
        for (int dy = 0; dy < 2; dy++)
            #pragma unroll
            for (int dx = 0; dx < 2; dx++) {
                float v = acc[q][dy][dx] + bias;
                ls += v;
                lq = fmaf(v, v, lq);
                mx = fmaxf(mx, v);
            }
        g_pool2[((size_t)n * 64 + oc) * 16 + ty * 4 + tx] = mx;
        atomicAdd(&ssum[oc], ls);
        atomicAdd(&ssq[oc], lq);
    }
    __syncthreads();
    if (tid < 64) { atomicAdd(&g_sum2[tid], ssum[tid]); atomicAdd(&g_sq2[tid], ssq[tid]); }
}

// ---------------- fc1: tiled SGEMM 128x64x16, A = relu(bn(pool2)) on load -----
// grid (32,8), block 256; micro-tile 8(m) x 4(n) per thread
__global__ __launch_bounds__(256) void fc1_kernel(const float* __restrict__ bf1) {
    __shared__ __align__(16) float As[16 * 132];  // [k][m], padded
    __shared__ __align__(16) float Bs[16 * 68];   // [k][j], padded
    __shared__ float cs[64], cq[64];
    int tid = threadIdx.x;
    int m0 = blockIdx.x * 128, j0 = blockIdx.y * 64;
    int ty = tid >> 4, tx = tid & 15;
    if (tid < 64) { cs[tid] = 0.f; cq[tid] = 0.f; }

    float c[8][4];
    #pragma unroll
    for (int r = 0; r < 8; r++)
        #pragma unroll
        for (int q = 0; q < 4; q++) c[r][q] = 0.f;

    for (int kt = 0; kt < 64; kt++) {            // k-tile == channel (16 elems)
        float sc = g_a2[kt], sd = g_d2[kt];
        #pragma unroll
        for (int s = 0; s < 8; s++) {
            int idx = s * 256 + tid, ml = idx >> 4, kl = idx & 15;
            float raw = g_pool2[(size_t)(m0 + ml) * 1024 + kt * 16 + kl];
            As[kl * 132 + ml] = fmaxf(fmaf(sc, raw, sd), 0.f);
        }
        #pragma unroll
        for (int s = 0; s < 4; s++) {
            int idx = s * 256 + tid, jl = idx >> 4, kl = idx & 15;
            Bs[kl * 68 + jl] = g_qf1[(size_t)(j0 + jl) * 1024 + kt * 16 + kl];
        }
        __syncthreads();
        #pragma unroll
        for (int k = 0; k < 16; k++) {
            float4 a0 = *reinterpret_cast<const float4*>(&As[k * 132 + ty * 8]);
            float4 a1 = *reinterpret_cast<const float4*>(&As[k * 132 + ty * 8 + 4]);
            float4 b  = *reinterpret_cast<const float4*>(&Bs[k * 68 + tx * 4]);
            float av[8] = {a0.x, a0.y, a0.z, a0.w, a1.x, a1.y, a1.z, a1.w};
            float bv[4] = {b.x, b.y, b.z, b.w};
            #pragma unroll
            for (int r = 0; r < 8; r++)
                #pragma unroll
                for (int q = 0; q < 4; q++) c[r][q] = fmaf(av[r], bv[q], c[r][q]);
        }
        __syncthreads();
    }

    float bias[4], ls[4] = {0, 0, 0, 0}, lq[4] = {0, 0, 0, 0};
    #pragma unroll
    for (int q = 0; q < 4; q++) bias[q] = bf1[j0 + tx * 4 + q];
    #pragma unroll
    for (int r = 0; r < 8; r++) {
        size_t row = (size_t)(m0 + ty * 8 + r);
        #pragma unroll
        for (int q = 0; q < 4; q++) {
            float v = c[r][q] + bias[q];
            g_z[row * 512 + j0 + tx * 4 + q] = v;
            ls[q] += v;
            lq[q] = fmaf(v, v, lq[q]);
        }
    }
    #pragma unroll
    for (int q = 0; q < 4; q++) { atomicAdd(&cs[tx * 4 + q], ls[q]); atomicAdd(&cq[tx * 4 + q], lq[q]); }
    __syncthreads();
    if (tid < 64) { atomicAdd(&g_sum3[j0 + tid], cs[tid]); atomicAdd(&g_sq3[j0 + tid], cq[tid]); }
}

// ---------------- fc2: [4096,512] x [512,10], one warp per row ----------------
__global__ __launch_bounds__(256) void fc2_kernel(const float* __restrict__ bf2,
                                                  float* __restrict__ out) {
    int w = threadIdx.x >> 5, l = threadIdx.x & 31;
    int row = blockIdx.x * 8 + w;
    const float* zr = g_z + (size_t)row * 512;
    float acc[10];
    #pragma unroll
    for (int k = 0; k < 10; k++) acc[k] = 0.f;
    for (int j = l; j < 512; j += 32) {
        float h = fmaxf(fmaf(g_a3[j], zr[j], g_d3[j]), 0.f);
        #pragma unroll
        for (int k = 0; k < 10; k++) acc[k] = fmaf(h, g_qf2[k * 512 + j], acc[k]);
    }
    #pragma unroll
    for (int k = 0; k < 10; k++)
        #pragma unroll
        for (int o = 16; o; o >>= 1) acc[k] += __shfl_xor_sync(0xffffffffu, acc[k], o);
    if (l < 10) out[row * 10 + l] = acc[l] + bf2[l];
}

// ---------------- host entry ----------------
extern "C" void kernel_launch(void* const* d_in, const int* in_sizes, int n_in,
                              void* d_out, int out_size) {
    const float* x   = (const float*)d_in[0];
    const float* w1  = (const float*)d_in[1];
    const float* b1  = (const float*)d_in[2];
    const float* g1  = (const float*)d_in[3];
    const float* be1 = (const float*)d_in[4];
    const float* w2  = (const float*)d_in[5];
    const float* b2  = (const float*)d_in[6];
    const float* g2  = (const float*)d_in[7];
    const float* be2 = (const float*)d_in[8];
    const float* wf1 = (const float*)d_in[9];
    const float* bf1 = (const float*)d_in[10];
    const float* g3  = (const float*)d_in[11];
    const float* be3 = (const float*)d_in[12];
    const float* wf2 = (const float*)d_in[13];
    const float* bf2 = (const float*)d_in[14];
    float* out = (float*)d_out;

    zero_stats_kernel<<<1, 512>>>();

    // maxabs reductions (grid-wide, deterministic atomicMax on uint bits)
    maxabs_kernel<<<1,   256>>>(w1,  800,    0);
    maxabs_kernel<<<32,  256>>>(w2,  51200,  1);
    maxabs_kernel<<<256, 256>>>(wf1, 524288, 2);
    maxabs_kernel<<<4,   256>>>(wf2, 5120,   3);

    // quantize passes (fully parallel)
    quantize_kernel<<<4,    256>>>(w1,  800,    0);
    quantize_w2_kernel<<<200, 256>>>(w2);
    quantize_kernel<<<2048, 256>>>(wf1, 524288, 2);
    quantize_kernel<<<20,   256>>>(wf2, 5120,   3);

    conv1_kernel<<<NIMG, 256>>>(x, b1);
    finalize_kernel<<<1, 32>>>(g1, be1, 0);

    conv2_kernel<<<NIMG, 256>>>(b2);
    finalize_kernel<<<1, 64>>>(g2, be2, 1);

    fc1_kernel<<<dim3(32, 8), 256>>>(bf1);
    finalize_kernel<<<2, 256>>>(g3, be3, 2);

    fc2_kernel<<<512, 256>>>(bf2, out);
}